// round 9
// baseline (speedup 1.0000x reference)
#include <cuda_runtime.h>
#include <cuda_bf16.h>

#define N_NODES_MAX 100000
#define E_MAX 1600000
#define IN_CH 128
#define HID 64
#define N_CLASSES 16
#define N_GRAPHS 64

// Scratch (device globals; no allocation allowed).
__device__ __align__(256) float g_dis[N_NODES_MAX];                 // deg -> rsqrt(deg)
__device__ __align__(256) float g_bufA[(size_t)N_NODES_MAX * HID];  // 25.6 MB (gemm out)
__device__ __align__(256) float g_bufB[(size_t)N_NODES_MAX * HID];  // 25.6 MB (layer out)
__device__ __align__(256) float g_pool[N_GRAPHS * HID];
__device__ __align__(256) float g_cnt[N_GRAPHS];
// CSR by destination
__device__ __align__(256) int   g_cnt_i[N_NODES_MAX];
__device__ __align__(256) int   g_rowtmp[N_NODES_MAX];
__device__ __align__(256) int   g_rowptr[N_NODES_MAX + 1];
__device__ __align__(256) int   g_fill[N_NODES_MAX];
__device__ __align__(256) int   g_bsums[128];
__device__ __align__(256) int   g_bsums_ex[128];
__device__ __align__(256) int2  g_edge[E_MAX];                      // {src, bits(w)}

__device__ __forceinline__ void dot4(float& ac, const float4& a, const float4& b) {
    ac = fmaf(a.x, b.x, ac);
    ac = fmaf(a.y, b.y, ac);
    ac = fmaf(a.z, b.z, ac);
    ac = fmaf(a.w, b.w, ac);
}

// ---------------- init: deg=1 (self loop), counts=0, pool zero ----------------
__global__ void k_init(int N) {
    int i = blockIdx.x * blockDim.x + threadIdx.x;
    if (i < N) { g_dis[i] = 1.0f; g_cnt_i[i] = 0; }
    if (i < N_GRAPHS * HID) g_pool[i] = 0.f;
    if (i < N_GRAPHS) g_cnt[i] = 0.f;
}

// ---------------- per-edge: count + weighted degree ----------------
__global__ void k_count_deg(const int* __restrict__ ei,
                            const float* __restrict__ ew, int E) {
    int e = blockIdx.x * blockDim.x + threadIdx.x;
    if (e < E) {
        int d = ei[E + e];
        atomicAdd(&g_cnt_i[d], 1);
        atomicAdd(&g_dis[d], ew[e]);
    }
}

// ---------------- prefix scan (3 kernels) ----------------
__global__ __launch_bounds__(1024) void k_scan1(int N) {
    __shared__ int sh[1024];
    int i = blockIdx.x * 1024 + threadIdx.x;
    int v = (i < N) ? g_cnt_i[i] : 0;
    sh[threadIdx.x] = v;
    __syncthreads();
    for (int off = 1; off < 1024; off <<= 1) {
        int t = (threadIdx.x >= off) ? sh[threadIdx.x - off] : 0;
        __syncthreads();
        sh[threadIdx.x] += t;
        __syncthreads();
    }
    if (i < N) g_rowtmp[i] = sh[threadIdx.x] - v;  // exclusive
    if (threadIdx.x == 1023) g_bsums[blockIdx.x] = sh[1023];
}

__global__ void k_scan2(int nb) {
    __shared__ int sh[128];
    int t = threadIdx.x;
    sh[t] = (t < nb) ? g_bsums[t] : 0;
    __syncthreads();
    if (t == 0) {
        int run = 0;
        for (int k = 0; k < nb; k++) { int c = sh[k]; sh[k] = run; run += c; }
    }
    __syncthreads();
    if (t < nb) g_bsums_ex[t] = sh[t];
}

// rowptr = rowtmp + block offset; also fill cursor init and dis=rsqrt(deg)
__global__ void k_scan3(int N, int E) {
    int i = blockIdx.x * blockDim.x + threadIdx.x;
    if (i < N) {
        int rp = g_rowtmp[i] + g_bsums_ex[i >> 10];
        g_rowptr[i] = rp;
        g_fill[i] = rp;
        g_dis[i] = rsqrtf(g_dis[i]);
    }
    if (i == 0) g_rowptr[N] = E;
}

// ---------------- fill CSR: edge -> slot ----------------
__global__ void k_fill(const int* __restrict__ ei,
                       const float* __restrict__ ew, int E) {
    int e = blockIdx.x * blockDim.x + threadIdx.x;
    if (e < E) {
        int d = ei[E + e];
        int slot = atomicAdd(&g_fill[d], 1);
        g_edge[slot] = make_int2(ei[e], __float_as_int(ew[e]));
    }
}

// ---------------- GEMM: bufA = (X @ W) * dis[row] ----------------
// src==0: X = Xext (input features). src==1: X = g_bufB (prev layer out).
template <int K>
__global__ __launch_bounds__(256) void k_gemm(const float* Xext, const float* __restrict__ W,
                                              int N, int src) {
    const int S = 68;  // padded smem row stride (floats)
    __shared__ float Xs[64 * S];
    __shared__ float Ws[64 * S];  // transposed: Ws[c][k]

    const float* X = (src == 0) ? Xext : g_bufB;
    int t = threadIdx.x;
    int rowbase = blockIdx.x * 64;
    int cc = t & 15;
    int rr = t >> 4;

    float acc[4][4] = {};

    for (int kc = 0; kc < K; kc += 64) {
        for (int f4 = t; f4 < 1024; f4 += 256) {
            int r = f4 >> 4;
            int kq = (f4 & 15) << 2;
            int row = rowbase + r;
            float4 v = make_float4(0.f, 0.f, 0.f, 0.f);
            if (row < N) v = *(const float4*)(X + (size_t)row * K + kc + kq);
            *(float4*)(Xs + r * S + kq) = v;
        }
        for (int f = t; f < 4096; f += 256) {
            int kl = f >> 6;
            int c = f & 63;
            Ws[c * S + kl] = W[(size_t)(kc + kl) * 64 + c];
        }
        __syncthreads();

#pragma unroll
        for (int kl = 0; kl < 64; kl += 4) {
            float4 a0 = *(const float4*)(Xs + (rr * 4 + 0) * S + kl);
            float4 a1 = *(const float4*)(Xs + (rr * 4 + 1) * S + kl);
            float4 a2 = *(const float4*)(Xs + (rr * 4 + 2) * S + kl);
            float4 a3 = *(const float4*)(Xs + (rr * 4 + 3) * S + kl);
            float4 w0 = *(const float4*)(Ws + (cc + 0) * S + kl);
            float4 w1 = *(const float4*)(Ws + (cc + 16) * S + kl);
            float4 w2 = *(const float4*)(Ws + (cc + 32) * S + kl);
            float4 w3 = *(const float4*)(Ws + (cc + 48) * S + kl);
            dot4(acc[0][0], a0, w0); dot4(acc[0][1], a0, w1); dot4(acc[0][2], a0, w2); dot4(acc[0][3], a0, w3);
            dot4(acc[1][0], a1, w0); dot4(acc[1][1], a1, w1); dot4(acc[1][2], a1, w2); dot4(acc[1][3], a1, w3);
            dot4(acc[2][0], a2, w0); dot4(acc[2][1], a2, w1); dot4(acc[2][2], a2, w2); dot4(acc[2][3], a2, w3);
            dot4(acc[3][0], a3, w0); dot4(acc[3][1], a3, w1); dot4(acc[3][2], a3, w2); dot4(acc[3][3], a3, w3);
        }
        __syncthreads();
    }

#pragma unroll
    for (int i = 0; i < 4; i++) {
        int row = rowbase + rr * 4 + i;
        if (row < N) {
            float ds = g_dis[row];
#pragma unroll
            for (int j = 0; j < 4; j++) {
                int c = cc + 16 * j;
                g_bufA[(size_t)row * HID + c] = acc[i][j] * ds;
            }
        }
    }
}

// ---------------- gather + dis + bias + relu (pull-mode aggregation) ----------------
// One warp per node, 32 lanes x float2, edge loop unrolled by 4 for MLP.
// bufA -> bufB.  acc init = g[node] (self loop, weight 1).
__global__ __launch_bounds__(256) void k_gather(const float* __restrict__ bias, int N) {
    int node = (blockIdx.x * 256 + threadIdx.x) >> 5;
    if (node >= N) return;
    int lane = threadIdx.x & 31;

    const float2* G = (const float2*)g_bufA;
    int base = node * 32 + lane;
    float2 acc = G[base];

    int k = __ldg(&g_rowptr[node]);
    int s1 = __ldg(&g_rowptr[node + 1]);

    // main loop: 4 independent gathers in flight
    for (; k + 3 < s1; k += 4) {
        int2 e0 = g_edge[k];
        int2 e1 = g_edge[k + 1];
        int2 e2 = g_edge[k + 2];
        int2 e3 = g_edge[k + 3];
        float2 v0 = G[e0.x * 32 + lane];
        float2 v1 = G[e1.x * 32 + lane];
        float2 v2 = G[e2.x * 32 + lane];
        float2 v3 = G[e3.x * 32 + lane];
        float w0 = __int_as_float(e0.y);
        float w1 = __int_as_float(e1.y);
        float w2 = __int_as_float(e2.y);
        float w3 = __int_as_float(e3.y);
        acc.x = fmaf(w0, v0.x, acc.x); acc.y = fmaf(w0, v0.y, acc.y);
        acc.x = fmaf(w1, v1.x, acc.x); acc.y = fmaf(w1, v1.y, acc.y);
        acc.x = fmaf(w2, v2.x, acc.x); acc.y = fmaf(w2, v2.y, acc.y);
        acc.x = fmaf(w3, v3.x, acc.x); acc.y = fmaf(w3, v3.y, acc.y);
    }
    for (; k < s1; k++) {
        int2 e0 = g_edge[k];
        float2 v0 = G[e0.x * 32 + lane];
        float w0 = __int_as_float(e0.y);
        acc.x = fmaf(w0, v0.x, acc.x); acc.y = fmaf(w0, v0.y, acc.y);
    }

    float ds = g_dis[node];
    float bx = bias[lane * 2];
    float by = bias[lane * 2 + 1];
    float ox = fmaf(ds, acc.x, bx);
    float oy = fmaf(ds, acc.y, by);
    float2 o;
    o.x = ox > 0.f ? ox : 0.f;
    o.y = oy > 0.f ? oy : 0.f;
    ((float2*)g_bufB)[base] = o;
}

// ---------------- pooling ----------------
#define POOL_CHUNK 2048
__global__ __launch_bounds__(256) void k_pool(const int* __restrict__ batch, int N) {
    int base = blockIdx.x * POOL_CHUNK;
    int c = threadIdx.x & 63;
    int r0 = threadIdx.x >> 6;  // 0..3
    int end = base + POOL_CHUNK;
    if (end > N) end = N;

    float s = 0.f, n = 0.f;
    int cur = -1;
    for (int i = base + r0; i < end; i += 4) {
        int gi = batch[i];
        if (gi != cur) {
            if (cur >= 0) {
                atomicAdd(g_pool + cur * 64 + c, s);
                if (c == 0) atomicAdd(g_cnt + cur, n);
            }
            cur = gi; s = 0.f; n = 0.f;
        }
        s += g_bufB[(size_t)i * HID + c];
        n += 1.f;
    }
    if (cur >= 0) {
        atomicAdd(g_pool + cur * 64 + c, s);
        if (c == 0) atomicAdd(g_cnt + cur, n);
    }
}

// ---------------- head ----------------
__global__ void k_head(const float* __restrict__ Wl, const float* __restrict__ bl,
                       float* __restrict__ out) {
    int t = threadIdx.x;
    if (t >= N_GRAPHS * N_CLASSES) return;
    int g = t >> 4;
    int j = t & 15;
    float inv = 1.f / fmaxf(g_cnt[g], 1.f);
    float a = bl[j];
#pragma unroll
    for (int c = 0; c < 64; c++)
        a = fmaf(g_pool[g * 64 + c] * inv, Wl[c * 16 + j], a);
    out[t] = a;
}

// ---------------- launch ----------------
extern "C" void kernel_launch(void* const* d_in, const int* in_sizes, int n_in,
                              void* d_out, int out_size) {
    const float* x = (const float*)d_in[0];
    const int* ei = (const int*)d_in[1];      // int32 (JAX x64 disabled)
    const float* ew = (const float*)d_in[2];
    const int* batch = (const int*)d_in[3];   // int32
    const float* W1 = (const float*)d_in[4];
    const float* b1 = (const float*)d_in[5];
    const float* W2 = (const float*)d_in[6];
    const float* b2 = (const float*)d_in[7];
    const float* Wl = (const float*)d_in[8];
    const float* bl = (const float*)d_in[9];
    float* out = (float*)d_out;

    int N = in_sizes[0] / IN_CH;   // 100000
    int E = in_sizes[2];           // 1600000

    int tb = 256;
    int nblk = (N + tb - 1) / tb;
    int eblk = (E + tb - 1) / tb;
    int nb_scan = (N + 1023) / 1024;

    // ---- CSR build + degree ----
    k_init<<<nblk, tb>>>(N);
    k_count_deg<<<eblk, tb>>>(ei, ew, E);
    k_scan1<<<nb_scan, 1024>>>(N);
    k_scan2<<<1, 128>>>(nb_scan);
    k_scan3<<<nblk, tb>>>(N, E);
    k_fill<<<eblk, tb>>>(ei, ew, E);

    int gemm_blocks = (N + 63) / 64;
    int gather_blocks = (N * 32 + tb - 1) / tb;

    // layer 1
    k_gemm<IN_CH><<<gemm_blocks, tb>>>(x, W1, N, 0);   // A = (x@W1)*dis
    k_gather<<<gather_blocks, tb>>>(b1, N);            // B = relu(dis*(agg A) + b1)

    // layer 2
    k_gemm<HID><<<gemm_blocks, tb>>>(nullptr, W2, N, 1); // A = (B@W2)*dis
    k_gather<<<gather_blocks, tb>>>(b2, N);              // B = relu(dis*(agg A) + b2)

    // pooling + head
    k_pool<<<(N + POOL_CHUNK - 1) / POOL_CHUNK, tb>>>(batch, N);
    k_head<<<1, 1024>>>(Wl, bl, out);
}

// round 10
// speedup vs baseline: 1.0764x; 1.0764x over previous
#include <cuda_runtime.h>
#include <cuda_fp16.h>

#define N_NODES_MAX 100000
#define E_MAX 1600000
#define IN_CH 128
#define HID 64
#define N_CLASSES 16
#define N_GRAPHS 64

// Scratch (device globals; no allocation allowed).
__device__ __align__(256) float  g_dis[N_NODES_MAX];                 // deg -> rsqrt(deg)
__device__ __align__(256) __half g_bufA[(size_t)N_NODES_MAX * HID];  // 12.8 MB (gemm out, fp16)
__device__ __align__(256) float  g_bufB[(size_t)N_NODES_MAX * HID];  // 25.6 MB (layer out)
__device__ __align__(256) float  g_pool[N_GRAPHS * HID];
__device__ __align__(256) float  g_cnt[N_GRAPHS];
// CSR by destination
__device__ __align__(256) int    g_cnt_i[N_NODES_MAX];
__device__ __align__(256) int    g_rowtmp[N_NODES_MAX];
__device__ __align__(256) int    g_rowptr[N_NODES_MAX + 1];
__device__ __align__(256) int    g_fill[N_NODES_MAX];
__device__ __align__(256) int    g_bsums[128];
__device__ __align__(256) int    g_bsums_ex[128];
__device__ __align__(256) int2   g_edge[E_MAX];                      // {src, bits(w)}

__device__ __forceinline__ void dot4(float& ac, const float4& a, const float4& b) {
    ac = fmaf(a.x, b.x, ac);
    ac = fmaf(a.y, b.y, ac);
    ac = fmaf(a.z, b.z, ac);
    ac = fmaf(a.w, b.w, ac);
}

// ---------------- init: deg=1 (self loop), counts=0, pool zero ----------------
__global__ void k_init(int N) {
    int i = blockIdx.x * blockDim.x + threadIdx.x;
    if (i < N) { g_dis[i] = 1.0f; g_cnt_i[i] = 0; }
    if (i < N_GRAPHS * HID) g_pool[i] = 0.f;
    if (i < N_GRAPHS) g_cnt[i] = 0.f;
}

// ---------------- per-edge: count + weighted degree ----------------
__global__ void k_count_deg(const int* __restrict__ ei,
                            const float* __restrict__ ew, int E) {
    int e = blockIdx.x * blockDim.x + threadIdx.x;
    if (e < E) {
        int d = ei[E + e];
        atomicAdd(&g_cnt_i[d], 1);
        atomicAdd(&g_dis[d], ew[e]);
    }
}

// ---------------- prefix scan (3 kernels) ----------------
__global__ __launch_bounds__(1024) void k_scan1(int N) {
    __shared__ int sh[1024];
    int i = blockIdx.x * 1024 + threadIdx.x;
    int v = (i < N) ? g_cnt_i[i] : 0;
    sh[threadIdx.x] = v;
    __syncthreads();
    for (int off = 1; off < 1024; off <<= 1) {
        int t = (threadIdx.x >= off) ? sh[threadIdx.x - off] : 0;
        __syncthreads();
        sh[threadIdx.x] += t;
        __syncthreads();
    }
    if (i < N) g_rowtmp[i] = sh[threadIdx.x] - v;  // exclusive
    if (threadIdx.x == 1023) g_bsums[blockIdx.x] = sh[1023];
}

__global__ void k_scan2(int nb) {
    __shared__ int sh[128];
    int t = threadIdx.x;
    sh[t] = (t < nb) ? g_bsums[t] : 0;
    __syncthreads();
    if (t == 0) {
        int run = 0;
        for (int k = 0; k < nb; k++) { int c = sh[k]; sh[k] = run; run += c; }
    }
    __syncthreads();
    if (t < nb) g_bsums_ex[t] = sh[t];
}

// rowptr = rowtmp + block offset; also fill cursor init and dis=rsqrt(deg)
__global__ void k_scan3(int N, int E) {
    int i = blockIdx.x * blockDim.x + threadIdx.x;
    if (i < N) {
        int rp = g_rowtmp[i] + g_bsums_ex[i >> 10];
        g_rowptr[i] = rp;
        g_fill[i] = rp;
        g_dis[i] = rsqrtf(g_dis[i]);
    }
    if (i == 0) g_rowptr[N] = E;
}

// ---------------- fill CSR: edge -> slot ----------------
__global__ void k_fill(const int* __restrict__ ei,
                       const float* __restrict__ ew, int E) {
    int e = blockIdx.x * blockDim.x + threadIdx.x;
    if (e < E) {
        int d = ei[E + e];
        int slot = atomicAdd(&g_fill[d], 1);
        g_edge[slot] = make_int2(ei[e], __float_as_int(ew[e]));
    }
}

// ---------------- GEMM: bufA = half( (X @ W) * dis[row] ) ----------------
// src==0: X = Xext (input features). src==1: X = g_bufB (prev layer out).
template <int K>
__global__ __launch_bounds__(256) void k_gemm(const float* Xext, const float* __restrict__ W,
                                              int N, int src) {
    const int S = 68;  // padded smem row stride (floats)
    __shared__ float Xs[64 * S];
    __shared__ float Ws[64 * S];  // transposed: Ws[c][k]

    const float* X = (src == 0) ? Xext : g_bufB;
    int t = threadIdx.x;
    int rowbase = blockIdx.x * 64;
    int cc = t & 15;
    int rr = t >> 4;

    float acc[4][4] = {};

    for (int kc = 0; kc < K; kc += 64) {
        for (int f4 = t; f4 < 1024; f4 += 256) {
            int r = f4 >> 4;
            int kq = (f4 & 15) << 2;
            int row = rowbase + r;
            float4 v = make_float4(0.f, 0.f, 0.f, 0.f);
            if (row < N) v = *(const float4*)(X + (size_t)row * K + kc + kq);
            *(float4*)(Xs + r * S + kq) = v;
        }
        for (int f = t; f < 4096; f += 256) {
            int kl = f >> 6;
            int c = f & 63;
            Ws[c * S + kl] = W[(size_t)(kc + kl) * 64 + c];
        }
        __syncthreads();

#pragma unroll
        for (int kl = 0; kl < 64; kl += 4) {
            float4 a0 = *(const float4*)(Xs + (rr * 4 + 0) * S + kl);
            float4 a1 = *(const float4*)(Xs + (rr * 4 + 1) * S + kl);
            float4 a2 = *(const float4*)(Xs + (rr * 4 + 2) * S + kl);
            float4 a3 = *(const float4*)(Xs + (rr * 4 + 3) * S + kl);
            float4 w0 = *(const float4*)(Ws + (cc + 0) * S + kl);
            float4 w1 = *(const float4*)(Ws + (cc + 16) * S + kl);
            float4 w2 = *(const float4*)(Ws + (cc + 32) * S + kl);
            float4 w3 = *(const float4*)(Ws + (cc + 48) * S + kl);
            dot4(acc[0][0], a0, w0); dot4(acc[0][1], a0, w1); dot4(acc[0][2], a0, w2); dot4(acc[0][3], a0, w3);
            dot4(acc[1][0], a1, w0); dot4(acc[1][1], a1, w1); dot4(acc[1][2], a1, w2); dot4(acc[1][3], a1, w3);
            dot4(acc[2][0], a2, w0); dot4(acc[2][1], a2, w1); dot4(acc[2][2], a2, w2); dot4(acc[2][3], a2, w3);
            dot4(acc[3][0], a3, w0); dot4(acc[3][1], a3, w1); dot4(acc[3][2], a3, w2); dot4(acc[3][3], a3, w3);
        }
        __syncthreads();
    }

#pragma unroll
    for (int i = 0; i < 4; i++) {
        int row = rowbase + rr * 4 + i;
        if (row < N) {
            float ds = g_dis[row];
#pragma unroll
            for (int j = 0; j < 4; j++) {
                int c = cc + 16 * j;
                g_bufA[(size_t)row * HID + c] = __float2half(acc[i][j] * ds);
            }
        }
    }
}

// ---------------- gather + dis + bias + relu (pull-mode aggregation) ----------------
// One warp per node, 32 lanes x half2 (128B/node = 1 L2 line). bufA(fp16) -> bufB(fp32).
// acc init = g[node] (self loop, weight 1).
__global__ __launch_bounds__(256) void k_gather(const float* __restrict__ bias, int N) {
    int node = (blockIdx.x * 256 + threadIdx.x) >> 5;
    if (node >= N) return;
    int lane = threadIdx.x & 31;

    const __half2* G = (const __half2*)g_bufA;
    int base = node * 32 + lane;
    float2 acc = __half22float2(G[base]);

    int k = __ldg(&g_rowptr[node]);
    int s1 = __ldg(&g_rowptr[node + 1]);
    for (; k + 1 < s1; k += 2) {
        int2 e0 = g_edge[k];
        int2 e1 = g_edge[k + 1];
        float2 v0 = __half22float2(G[e0.x * 32 + lane]);
        float2 v1 = __half22float2(G[e1.x * 32 + lane]);
        float w0 = __int_as_float(e0.y);
        float w1 = __int_as_float(e1.y);
        acc.x = fmaf(w0, v0.x, acc.x); acc.y = fmaf(w0, v0.y, acc.y);
        acc.x = fmaf(w1, v1.x, acc.x); acc.y = fmaf(w1, v1.y, acc.y);
    }
    if (k < s1) {
        int2 e0 = g_edge[k];
        float2 v0 = __half22float2(G[e0.x * 32 + lane]);
        float w0 = __int_as_float(e0.y);
        acc.x = fmaf(w0, v0.x, acc.x); acc.y = fmaf(w0, v0.y, acc.y);
    }

    float ds = g_dis[node];
    float bx = bias[lane * 2];
    float by = bias[lane * 2 + 1];
    float ox = fmaf(ds, acc.x, bx);
    float oy = fmaf(ds, acc.y, by);
    float2 o;
    o.x = ox > 0.f ? ox : 0.f;
    o.y = oy > 0.f ? oy : 0.f;
    ((float2*)g_bufB)[base] = o;
}

// ---------------- pooling ----------------
#define POOL_CHUNK 2048
__global__ __launch_bounds__(256) void k_pool(const int* __restrict__ batch, int N) {
    int base = blockIdx.x * POOL_CHUNK;
    int c = threadIdx.x & 63;
    int r0 = threadIdx.x >> 6;  // 0..3
    int end = base + POOL_CHUNK;
    if (end > N) end = N;

    float s = 0.f, n = 0.f;
    int cur = -1;
    for (int i = base + r0; i < end; i += 4) {
        int gi = batch[i];
        if (gi != cur) {
            if (cur >= 0) {
                atomicAdd(g_pool + cur * 64 + c, s);
                if (c == 0) atomicAdd(g_cnt + cur, n);
            }
            cur = gi; s = 0.f; n = 0.f;
        }
        s += g_bufB[(size_t)i * HID + c];
        n += 1.f;
    }
    if (cur >= 0) {
        atomicAdd(g_pool + cur * 64 + c, s);
        if (c == 0) atomicAdd(g_cnt + cur, n);
    }
}

// ---------------- head ----------------
__global__ void k_head(const float* __restrict__ Wl, const float* __restrict__ bl,
                       float* __restrict__ out) {
    int t = threadIdx.x;
    if (t >= N_GRAPHS * N_CLASSES) return;
    int g = t >> 4;
    int j = t & 15;
    float inv = 1.f / fmaxf(g_cnt[g], 1.f);
    float a = bl[j];
#pragma unroll
    for (int c = 0; c < 64; c++)
        a = fmaf(g_pool[g * 64 + c] * inv, Wl[c * 16 + j], a);
    out[t] = a;
}

// ---------------- launch ----------------
extern "C" void kernel_launch(void* const* d_in, const int* in_sizes, int n_in,
                              void* d_out, int out_size) {
    const float* x = (const float*)d_in[0];
    const int* ei = (const int*)d_in[1];      // int32 (JAX x64 disabled)
    const float* ew = (const float*)d_in[2];
    const int* batch = (const int*)d_in[3];   // int32
    const float* W1 = (const float*)d_in[4];
    const float* b1 = (const float*)d_in[5];
    const float* W2 = (const float*)d_in[6];
    const float* b2 = (const float*)d_in[7];
    const float* Wl = (const float*)d_in[8];
    const float* bl = (const float*)d_in[9];
    float* out = (float*)d_out;

    int N = in_sizes[0] / IN_CH;   // 100000
    int E = in_sizes[2];           // 1600000

    int tb = 256;
    int nblk = (N + tb - 1) / tb;
    int eblk = (E + tb - 1) / tb;
    int nb_scan = (N + 1023) / 1024;

    // ---- CSR build + degree ----
    k_init<<<nblk, tb>>>(N);
    k_count_deg<<<eblk, tb>>>(ei, ew, E);
    k_scan1<<<nb_scan, 1024>>>(N);
    k_scan2<<<1, 128>>>(nb_scan);
    k_scan3<<<nblk, tb>>>(N, E);
    k_fill<<<eblk, tb>>>(ei, ew, E);

    int gemm_blocks = (N + 63) / 64;
    int gather_blocks = (N * 32 + tb - 1) / tb;

    // layer 1
    k_gemm<IN_CH><<<gemm_blocks, tb>>>(x, W1, N, 0);   // A = half((x@W1)*dis)
    k_gather<<<gather_blocks, tb>>>(b1, N);            // B = relu(dis*(agg A) + b1)

    // layer 2
    k_gemm<HID><<<gemm_blocks, tb>>>(nullptr, W2, N, 1); // A = half((B@W2)*dis)
    k_gather<<<gather_blocks, tb>>>(b2, N);              // B = relu(dis*(agg A) + b2)

    // pooling + head
    k_pool<<<(N + POOL_CHUNK - 1) / POOL_CHUNK, tb>>>(batch, N);
    k_head<<<1, 1024>>>(Wl, bl, out);
}

// round 11
// speedup vs baseline: 1.6416x; 1.5251x over previous
#include <cuda_runtime.h>
#include <cuda_fp16.h>

#define N_NODES_MAX 100000
#define E_MAX 1600000
#define IN_CH 128
#define HID 64
#define N_CLASSES 16
#define N_GRAPHS 64

// Scratch (device globals; no allocation allowed).
__device__ __align__(256) float  g_dis[N_NODES_MAX];                 // deg -> rsqrt(deg)
__device__ __align__(256) __half g_bufA[(size_t)N_NODES_MAX * HID];  // 12.8 MB (gemm out, fp16)
__device__ __align__(256) float  g_bufB[(size_t)N_NODES_MAX * HID];  // 25.6 MB (layer out)
__device__ __align__(256) float  g_pool[N_GRAPHS * HID];
__device__ __align__(256) float  g_cnt[N_GRAPHS];
// CSR by destination
__device__ __align__(256) int    g_cnt_i[N_NODES_MAX];
__device__ __align__(256) int    g_rowtmp[N_NODES_MAX];
__device__ __align__(256) int    g_rowptr[N_NODES_MAX + 1];
__device__ __align__(256) int    g_fill[N_NODES_MAX];
__device__ __align__(256) int    g_bsums[128];
__device__ __align__(256) int2   g_edge[E_MAX];                      // {src, bits(w)}

__device__ __forceinline__ void dot4(float& ac, const float4& a, const float4& b) {
    ac = fmaf(a.x, b.x, ac);
    ac = fmaf(a.y, b.y, ac);
    ac = fmaf(a.z, b.z, ac);
    ac = fmaf(a.w, b.w, ac);
}

// ---------------- init: deg=1 (self loop), counts=0, pool zero ----------------
__global__ void k_init(int N) {
    int i = blockIdx.x * blockDim.x + threadIdx.x;
    if (i < N) { g_dis[i] = 1.0f; g_cnt_i[i] = 0; }
    if (i < N_GRAPHS * HID) g_pool[i] = 0.f;
    if (i < N_GRAPHS) g_cnt[i] = 0.f;
}

// ---------------- per-edge: count + weighted degree ----------------
__global__ void k_count_deg(const int* __restrict__ ei,
                            const float* __restrict__ ew, int E) {
    int e = blockIdx.x * blockDim.x + threadIdx.x;
    if (e < E) {
        int d = ei[E + e];
        atomicAdd(&g_cnt_i[d], 1);
        atomicAdd(&g_dis[d], ew[e]);
    }
}

// ---------------- prefix scan (2 kernels) ----------------
__global__ __launch_bounds__(1024) void k_scan1(int N) {
    __shared__ int sh[1024];
    int i = blockIdx.x * 1024 + threadIdx.x;
    int v = (i < N) ? g_cnt_i[i] : 0;
    sh[threadIdx.x] = v;
    __syncthreads();
    for (int off = 1; off < 1024; off <<= 1) {
        int t = (threadIdx.x >= off) ? sh[threadIdx.x - off] : 0;
        __syncthreads();
        sh[threadIdx.x] += t;
        __syncthreads();
    }
    if (i < N) g_rowtmp[i] = sh[threadIdx.x] - v;  // exclusive
    if (threadIdx.x == 1023) g_bsums[blockIdx.x] = sh[1023];
}

// rowptr = rowtmp + block-sum prefix (computed per-block in smem);
// also fill cursor init and dis=rsqrt(deg).
__global__ void k_scan3(int N, int E, int nb) {
    __shared__ int sh[128];
    int t = threadIdx.x;
    if (t < nb) sh[t] = g_bsums[t];
    __syncthreads();
    if (t == 0) {
        int run = 0;
        for (int j = 0; j < nb; j++) { int c = sh[j]; sh[j] = run; run += c; }
    }
    __syncthreads();
    int i = blockIdx.x * blockDim.x + t;
    if (i < N) {
        int rp = g_rowtmp[i] + sh[i >> 10];
        g_rowptr[i] = rp;
        g_fill[i] = rp;
        g_dis[i] = rsqrtf(g_dis[i]);
    }
    if (i == 0) g_rowptr[N] = E;
}

// ---------------- fill CSR: edge -> slot ----------------
__global__ void k_fill(const int* __restrict__ ei,
                       const float* __restrict__ ew, int E) {
    int e = blockIdx.x * blockDim.x + threadIdx.x;
    if (e < E) {
        int d = ei[E + e];
        int slot = atomicAdd(&g_fill[d], 1);
        g_edge[slot] = make_int2(ei[e], __float_as_int(ew[e]));
    }
}

// ---------------- GEMM: bufA = half( (X @ W) * dis[row] ) ----------------
// src==0: X = Xext (input features). src==1: X = g_bufB (prev layer out).
template <int K>
__global__ __launch_bounds__(256) void k_gemm(const float* Xext, const float* __restrict__ W,
                                              int N, int src) {
    const int S = 68;  // padded smem row stride (floats)
    __shared__ float Xs[64 * S];
    __shared__ float Ws[64 * S];  // transposed: Ws[c][k]

    const float* X = (src == 0) ? Xext : g_bufB;
    int t = threadIdx.x;
    int rowbase = blockIdx.x * 64;
    int cc = t & 15;
    int rr = t >> 4;

    float acc[4][4] = {};

    for (int kc = 0; kc < K; kc += 64) {
        for (int f4 = t; f4 < 1024; f4 += 256) {
            int r = f4 >> 4;
            int kq = (f4 & 15) << 2;
            int row = rowbase + r;
            float4 v = make_float4(0.f, 0.f, 0.f, 0.f);
            if (row < N) v = *(const float4*)(X + (size_t)row * K + kc + kq);
            *(float4*)(Xs + r * S + kq) = v;
        }
        for (int f = t; f < 4096; f += 256) {
            int kl = f >> 6;
            int c = f & 63;
            Ws[c * S + kl] = W[(size_t)(kc + kl) * 64 + c];
        }
        __syncthreads();

#pragma unroll
        for (int kl = 0; kl < 64; kl += 4) {
            float4 a0 = *(const float4*)(Xs + (rr * 4 + 0) * S + kl);
            float4 a1 = *(const float4*)(Xs + (rr * 4 + 1) * S + kl);
            float4 a2 = *(const float4*)(Xs + (rr * 4 + 2) * S + kl);
            float4 a3 = *(const float4*)(Xs + (rr * 4 + 3) * S + kl);
            float4 w0 = *(const float4*)(Ws + (cc + 0) * S + kl);
            float4 w1 = *(const float4*)(Ws + (cc + 16) * S + kl);
            float4 w2 = *(const float4*)(Ws + (cc + 32) * S + kl);
            float4 w3 = *(const float4*)(Ws + (cc + 48) * S + kl);
            dot4(acc[0][0], a0, w0); dot4(acc[0][1], a0, w1); dot4(acc[0][2], a0, w2); dot4(acc[0][3], a0, w3);
            dot4(acc[1][0], a1, w0); dot4(acc[1][1], a1, w1); dot4(acc[1][2], a1, w2); dot4(acc[1][3], a1, w3);
            dot4(acc[2][0], a2, w0); dot4(acc[2][1], a2, w1); dot4(acc[2][2], a2, w2); dot4(acc[2][3], a2, w3);
            dot4(acc[3][0], a3, w0); dot4(acc[3][1], a3, w1); dot4(acc[3][2], a3, w2); dot4(acc[3][3], a3, w3);
        }
        __syncthreads();
    }

#pragma unroll
    for (int i = 0; i < 4; i++) {
        int row = rowbase + rr * 4 + i;
        if (row < N) {
            float ds = g_dis[row];
#pragma unroll
            for (int j = 0; j < 4; j++) {
                int c = cc + 16 * j;
                g_bufA[(size_t)row * HID + c] = __float2half(acc[i][j] * ds);
            }
        }
    }
}

// ---------------- gather + dis + bias + relu (pull-mode, software-pipelined) ----------------
// One warp per node, 32 lanes x half2 (128B/node = 1 L2 line). bufA(fp16) -> bufB(fp32).
// Edge records for iteration i+1 are prefetched before the gathers of iteration i
// are consumed, overlapping the two L2 round-trips.
__global__ __launch_bounds__(256) void k_gather(const float* __restrict__ bias, int N) {
    int node = (blockIdx.x * 256 + threadIdx.x) >> 5;
    if (node >= N) return;
    int lane = threadIdx.x & 31;

    const __half2* G = (const __half2*)g_bufA;
    int base = node * 32 + lane;
    float2 acc = __half22float2(G[base]);

    int k = __ldg(&g_rowptr[node]);
    int s1 = __ldg(&g_rowptr[node + 1]);

    int2 e0, e1;
    bool have2 = (k + 1 < s1);
    if (have2) { e0 = g_edge[k]; e1 = g_edge[k + 1]; }
    while (have2) {
        int2 c0 = e0, c1 = e1;
        k += 2;
        have2 = (k + 1 < s1);
        if (have2) { e0 = g_edge[k]; e1 = g_edge[k + 1]; }  // prefetch next pair
        float2 v0 = __half22float2(G[c0.x * 32 + lane]);
        float2 v1 = __half22float2(G[c1.x * 32 + lane]);
        float w0 = __int_as_float(c0.y);
        float w1 = __int_as_float(c1.y);
        acc.x = fmaf(w0, v0.x, acc.x); acc.y = fmaf(w0, v0.y, acc.y);
        acc.x = fmaf(w1, v1.x, acc.x); acc.y = fmaf(w1, v1.y, acc.y);
    }
    if (k < s1) {  // at most one leftover edge
        int2 c0 = g_edge[k];
        float2 v0 = __half22float2(G[c0.x * 32 + lane]);
        float w0 = __int_as_float(c0.y);
        acc.x = fmaf(w0, v0.x, acc.x); acc.y = fmaf(w0, v0.y, acc.y);
    }

    float ds = g_dis[node];
    float bx = bias[lane * 2];
    float by = bias[lane * 2 + 1];
    float ox = fmaf(ds, acc.x, bx);
    float oy = fmaf(ds, acc.y, by);
    float2 o;
    o.x = ox > 0.f ? ox : 0.f;
    o.y = oy > 0.f ? oy : 0.f;
    ((float2*)g_bufB)[base] = o;
}

// ---------------- pooling (256-row chunks -> ~391 blocks for parallelism) ----------------
#define POOL_CHUNK 256
__global__ __launch_bounds__(256) void k_pool(const int* __restrict__ batch, int N) {
    int base = blockIdx.x * POOL_CHUNK;
    int c = threadIdx.x & 63;
    int r0 = threadIdx.x >> 6;  // 0..3
    int end = base + POOL_CHUNK;
    if (end > N) end = N;

    float s = 0.f, n = 0.f;
    int cur = -1;
    for (int i = base + r0; i < end; i += 4) {
        int gi = batch[i];
        if (gi != cur) {
            if (cur >= 0) {
                atomicAdd(g_pool + cur * 64 + c, s);
                if (c == 0) atomicAdd(g_cnt + cur, n);
            }
            cur = gi; s = 0.f; n = 0.f;
        }
        s += g_bufB[(size_t)i * HID + c];
        n += 1.f;
    }
    if (cur >= 0) {
        atomicAdd(g_pool + cur * 64 + c, s);
        if (c == 0) atomicAdd(g_cnt + cur, n);
    }
}

// ---------------- head ----------------
__global__ void k_head(const float* __restrict__ Wl, const float* __restrict__ bl,
                       float* __restrict__ out) {
    int t = threadIdx.x;
    if (t >= N_GRAPHS * N_CLASSES) return;
    int g = t >> 4;
    int j = t & 15;
    float inv = 1.f / fmaxf(g_cnt[g], 1.f);
    float a = bl[j];
#pragma unroll
    for (int c = 0; c < 64; c++)
        a = fmaf(g_pool[g * 64 + c] * inv, Wl[c * 16 + j], a);
    out[t] = a;
}

// ---------------- launch ----------------
extern "C" void kernel_launch(void* const* d_in, const int* in_sizes, int n_in,
                              void* d_out, int out_size) {
    const float* x = (const float*)d_in[0];
    const int* ei = (const int*)d_in[1];      // int32 (JAX x64 disabled)
    const float* ew = (const float*)d_in[2];
    const int* batch = (const int*)d_in[3];   // int32
    const float* W1 = (const float*)d_in[4];
    const float* b1 = (const float*)d_in[5];
    const float* W2 = (const float*)d_in[6];
    const float* b2 = (const float*)d_in[7];
    const float* Wl = (const float*)d_in[8];
    const float* bl = (const float*)d_in[9];
    float* out = (float*)d_out;

    int N = in_sizes[0] / IN_CH;   // 100000
    int E = in_sizes[2];           // 1600000

    int tb = 256;
    int nblk = (N + tb - 1) / tb;
    int eblk = (E + tb - 1) / tb;
    int nb_scan = (N + 1023) / 1024;

    // ---- CSR build + degree ----
    k_init<<<nblk, tb>>>(N);
    k_count_deg<<<eblk, tb>>>(ei, ew, E);
    k_scan1<<<nb_scan, 1024>>>(N);
    k_scan3<<<nblk, tb>>>(N, E, nb_scan);
    k_fill<<<eblk, tb>>>(ei, ew, E);

    int gemm_blocks = (N + 63) / 64;
    int gather_blocks = (N * 32 + tb - 1) / tb;

    // layer 1
    k_gemm<IN_CH><<<gemm_blocks, tb>>>(x, W1, N, 0);   // A = half((x@W1)*dis)
    k_gather<<<gather_blocks, tb>>>(b1, N);            // B = relu(dis*(agg A) + b1)

    // layer 2
    k_gemm<HID><<<gemm_blocks, tb>>>(nullptr, W2, N, 1); // A = half((B@W2)*dis)
    k_gather<<<gather_blocks, tb>>>(b2, N);              // B = relu(dis*(agg A) + b2)

    // pooling + head
    k_pool<<<(N + POOL_CHUNK - 1) / POOL_CHUNK, tb>>>(batch, N);
    k_head<<<1, 1024>>>(Wl, bl, out);
}

// round 12
// speedup vs baseline: 2.0289x; 1.2359x over previous
#include <cuda_runtime.h>
#include <cuda_fp16.h>

#define N_NODES_MAX 100000
#define E_MAX 1600000
#define IN_CH 128
#define HID 64
#define N_CLASSES 16
#define N_GRAPHS 64

// Scratch (device globals; no allocation allowed).
__device__ __align__(256) float  g_dis[N_NODES_MAX];                 // deg -> rsqrt(deg)
__device__ __align__(256) __half g_bufA[(size_t)N_NODES_MAX * HID];  // 12.8 MB (gemm out, fp16)
__device__ __align__(256) __half g_bufB[(size_t)N_NODES_MAX * HID];  // 12.8 MB (layer out, fp16)
__device__ __align__(256) float  g_pool[N_GRAPHS * HID];
__device__ __align__(256) float  g_cnt[N_GRAPHS];
// CSR by destination
__device__ __align__(256) int    g_cnt_i[N_NODES_MAX];
__device__ __align__(256) int    g_rowtmp[N_NODES_MAX];
__device__ __align__(256) int    g_rowptr[N_NODES_MAX + 1];
__device__ __align__(256) int    g_fill[N_NODES_MAX];
__device__ __align__(256) int    g_bsums[128];
__device__ __align__(256) int2   g_edge[E_MAX];                      // {src, bits(w)}

// ---------------- init: deg=1 (self loop), counts=0, pool zero ----------------
__global__ void k_init(int N) {
    int i = blockIdx.x * blockDim.x + threadIdx.x;
    if (i < N) { g_dis[i] = 1.0f; g_cnt_i[i] = 0; }
    if (i < N_GRAPHS * HID) g_pool[i] = 0.f;
    if (i < N_GRAPHS) g_cnt[i] = 0.f;
}

// ---------------- per-edge: count + weighted degree ----------------
__global__ void k_count_deg(const int* __restrict__ ei,
                            const float* __restrict__ ew, int E) {
    int e = blockIdx.x * blockDim.x + threadIdx.x;
    if (e < E) {
        int d = ei[E + e];
        atomicAdd(&g_cnt_i[d], 1);
        atomicAdd(&g_dis[d], ew[e]);
    }
}

// ---------------- prefix scan ----------------
__global__ __launch_bounds__(1024) void k_scan1(int N) {
    __shared__ int sh[1024];
    int i = blockIdx.x * 1024 + threadIdx.x;
    int v = (i < N) ? g_cnt_i[i] : 0;
    sh[threadIdx.x] = v;
    __syncthreads();
    for (int off = 1; off < 1024; off <<= 1) {
        int t = (threadIdx.x >= off) ? sh[threadIdx.x - off] : 0;
        __syncthreads();
        sh[threadIdx.x] += t;
        __syncthreads();
    }
    if (i < N) g_rowtmp[i] = sh[threadIdx.x] - v;  // exclusive
    if (threadIdx.x == 1023) g_bsums[blockIdx.x] = sh[1023];
}

// rowptr = rowtmp + block-sum prefix (re-derived per block in smem);
// also fill cursor init and dis=rsqrt(deg).
__global__ void k_scan3(int N, int E, int nb) {
    __shared__ int sh[128];
    int t = threadIdx.x;
    if (t < nb) sh[t] = g_bsums[t];
    __syncthreads();
    if (t == 0) {
        int run = 0;
        for (int j = 0; j < nb; j++) { int c = sh[j]; sh[j] = run; run += c; }
    }
    __syncthreads();
    int i = blockIdx.x * blockDim.x + t;
    if (i < N) {
        int rp = g_rowtmp[i] + sh[i >> 10];
        g_rowptr[i] = rp;
        g_fill[i] = rp;
        g_dis[i] = rsqrtf(g_dis[i]);
    }
    if (i == 0) g_rowptr[N] = E;
}

// ---------------- fill CSR: edge -> slot ----------------
__global__ void k_fill(const int* __restrict__ ei,
                       const float* __restrict__ ew, int E) {
    int e = blockIdx.x * blockDim.x + threadIdx.x;
    if (e < E) {
        int d = ei[E + e];
        int slot = atomicAdd(&g_fill[d], 1);
        g_edge[slot] = make_int2(ei[e], __float_as_int(ew[e]));
    }
}

// ---------------- tensor-core GEMM: bufA = half( (X @ W) * dis[row] ) ----------------
// 128-row tile per block, 256 threads = 8 warps, each warp 16 rows x 64 cols.
// mma.sync.m16n8k16 fp16 x fp16 -> fp32. X/W converted to fp16 in smem.
// src==0: X = Xf (fp32, input features). src==1: X = g_bufB (fp16, prev layer).
template <int K>
__global__ __launch_bounds__(256) void k_gemm_tc(const float* __restrict__ Xf,
                                                 const float* __restrict__ W,
                                                 int N, int src) {
    const int SX = 72;  // smem stride (halves); 72*2B=144B -> conflict-free quad access
    __shared__ __half Xh[128 * SX];
    __shared__ __half Wh[64 * SX];

    int t = threadIdx.x;
    int rowbase = blockIdx.x * 128;
    int lane = t & 31;
    int gID = lane >> 2;   // 0..7
    int t4 = lane & 3;     // 0..3
    int m_local = (t >> 5) * 16;

    float acc[8][4] = {};

    for (int kc = 0; kc < K; kc += 64) {
        // load X chunk: 128 rows x 64 halves (2048 x uint2)
        for (int f = t; f < 2048; f += 256) {
            int r = f >> 4;            // 16 uint2 per row
            int q = (f & 15) << 2;     // half offset 0..60
            int row = rowbase + r;
            uint2 hv = make_uint2(0u, 0u);
            if (row < N) {
                if (src == 0) {
                    float4 v = *(const float4*)(Xf + (size_t)row * K + kc + q);
                    __half2 p0 = __floats2half2_rn(v.x, v.y);
                    __half2 p1 = __floats2half2_rn(v.z, v.w);
                    hv.x = *(unsigned*)&p0;
                    hv.y = *(unsigned*)&p1;
                } else {
                    hv = *(const uint2*)(g_bufB + (size_t)row * K + kc + q);
                }
            }
            *(uint2*)&Xh[r * SX + q] = hv;
        }
        // load W chunk transposed: Wh[n][k] (column-major K x 64)
        for (int f = t; f < 4096; f += 256) {
            int kl = f >> 6;
            int c = f & 63;
            Wh[c * SX + kl] = __float2half(W[(size_t)(kc + kl) * 64 + c]);
        }
        __syncthreads();

#pragma unroll
        for (int kk = 0; kk < 64; kk += 16) {
            unsigned a0 = *(unsigned*)&Xh[(m_local + gID) * SX + kk + t4 * 2];
            unsigned a1 = *(unsigned*)&Xh[(m_local + gID + 8) * SX + kk + t4 * 2];
            unsigned a2 = *(unsigned*)&Xh[(m_local + gID) * SX + kk + 8 + t4 * 2];
            unsigned a3 = *(unsigned*)&Xh[(m_local + gID + 8) * SX + kk + 8 + t4 * 2];
#pragma unroll
            for (int j = 0; j < 8; j++) {
                int n = j * 8 + gID;
                unsigned b0 = *(unsigned*)&Wh[n * SX + kk + t4 * 2];
                unsigned b1 = *(unsigned*)&Wh[n * SX + kk + 8 + t4 * 2];
                asm volatile(
                    "mma.sync.aligned.m16n8k16.row.col.f32.f16.f16.f32 "
                    "{%0,%1,%2,%3}, {%4,%5,%6,%7}, {%8,%9}, {%0,%1,%2,%3};"
                    : "+f"(acc[j][0]), "+f"(acc[j][1]), "+f"(acc[j][2]), "+f"(acc[j][3])
                    : "r"(a0), "r"(a1), "r"(a2), "r"(a3), "r"(b0), "r"(b1));
            }
        }
        __syncthreads();
    }

    // epilogue: scale by dis, store fp16
    int r0 = rowbase + m_local + gID;
    int r1 = r0 + 8;
    if (r0 < N) {
        float ds = g_dis[r0];
#pragma unroll
        for (int j = 0; j < 8; j++) {
            __half2 h = __floats2half2_rn(acc[j][0] * ds, acc[j][1] * ds);
            *(__half2*)&g_bufA[(size_t)r0 * HID + j * 8 + t4 * 2] = h;
        }
    }
    if (r1 < N) {
        float ds = g_dis[r1];
#pragma unroll
        for (int j = 0; j < 8; j++) {
            __half2 h = __floats2half2_rn(acc[j][2] * ds, acc[j][3] * ds);
            *(__half2*)&g_bufA[(size_t)r1 * HID + j * 8 + t4 * 2] = h;
        }
    }
}

// ---------------- gather + dis + bias + relu (pull-mode, software-pipelined) ----------------
// One warp per node, 32 lanes x half2 (128B/node = 1 L2 line). bufA(fp16) -> bufB(fp16).
__global__ __launch_bounds__(256) void k_gather(const float* __restrict__ bias, int N) {
    int node = (blockIdx.x * 256 + threadIdx.x) >> 5;
    if (node >= N) return;
    int lane = threadIdx.x & 31;

    const __half2* G = (const __half2*)g_bufA;
    int base = node * 32 + lane;
    float2 acc = __half22float2(G[base]);

    int k = __ldg(&g_rowptr[node]);
    int s1 = __ldg(&g_rowptr[node + 1]);

    int2 e0, e1;
    bool have2 = (k + 1 < s1);
    if (have2) { e0 = g_edge[k]; e1 = g_edge[k + 1]; }
    while (have2) {
        int2 c0 = e0, c1 = e1;
        k += 2;
        have2 = (k + 1 < s1);
        if (have2) { e0 = g_edge[k]; e1 = g_edge[k + 1]; }  // prefetch next pair
        float2 v0 = __half22float2(G[c0.x * 32 + lane]);
        float2 v1 = __half22float2(G[c1.x * 32 + lane]);
        float w0 = __int_as_float(c0.y);
        float w1 = __int_as_float(c1.y);
        acc.x = fmaf(w0, v0.x, acc.x); acc.y = fmaf(w0, v0.y, acc.y);
        acc.x = fmaf(w1, v1.x, acc.x); acc.y = fmaf(w1, v1.y, acc.y);
    }
    if (k < s1) {
        int2 c0 = g_edge[k];
        float2 v0 = __half22float2(G[c0.x * 32 + lane]);
        float w0 = __int_as_float(c0.y);
        acc.x = fmaf(w0, v0.x, acc.x); acc.y = fmaf(w0, v0.y, acc.y);
    }

    float ds = g_dis[node];
    float bx = bias[lane * 2];
    float by = bias[lane * 2 + 1];
    float ox = fmaf(ds, acc.x, bx);
    float oy = fmaf(ds, acc.y, by);
    ox = ox > 0.f ? ox : 0.f;
    oy = oy > 0.f ? oy : 0.f;
    ((__half2*)g_bufB)[base] = __floats2half2_rn(ox, oy);
}

// ---------------- pooling (256-row chunks) ----------------
#define POOL_CHUNK 256
__global__ __launch_bounds__(256) void k_pool(const int* __restrict__ batch, int N) {
    int base = blockIdx.x * POOL_CHUNK;
    int c = threadIdx.x & 63;
    int r0 = threadIdx.x >> 6;  // 0..3
    int end = base + POOL_CHUNK;
    if (end > N) end = N;

    float s = 0.f, n = 0.f;
    int cur = -1;
    for (int i = base + r0; i < end; i += 4) {
        int gi = batch[i];
        if (gi != cur) {
            if (cur >= 0) {
                atomicAdd(g_pool + cur * 64 + c, s);
                if (c == 0) atomicAdd(g_cnt + cur, n);
            }
            cur = gi; s = 0.f; n = 0.f;
        }
        s += __half2float(g_bufB[(size_t)i * HID + c]);
        n += 1.f;
    }
    if (cur >= 0) {
        atomicAdd(g_pool + cur * 64 + c, s);
        if (c == 0) atomicAdd(g_cnt + cur, n);
    }
}

// ---------------- head ----------------
__global__ void k_head(const float* __restrict__ Wl, const float* __restrict__ bl,
                       float* __restrict__ out) {
    int t = threadIdx.x;
    if (t >= N_GRAPHS * N_CLASSES) return;
    int g = t >> 4;
    int j = t & 15;
    float inv = 1.f / fmaxf(g_cnt[g], 1.f);
    float a = bl[j];
#pragma unroll
    for (int c = 0; c < 64; c++)
        a = fmaf(g_pool[g * 64 + c] * inv, Wl[c * 16 + j], a);
    out[t] = a;
}

// ---------------- launch ----------------
extern "C" void kernel_launch(void* const* d_in, const int* in_sizes, int n_in,
                              void* d_out, int out_size) {
    const float* x = (const float*)d_in[0];
    const int* ei = (const int*)d_in[1];      // int32 (JAX x64 disabled)
    const float* ew = (const float*)d_in[2];
    const int* batch = (const int*)d_in[3];   // int32
    const float* W1 = (const float*)d_in[4];
    const float* b1 = (const float*)d_in[5];
    const float* W2 = (const float*)d_in[6];
    const float* b2 = (const float*)d_in[7];
    const float* Wl = (const float*)d_in[8];
    const float* bl = (const float*)d_in[9];
    float* out = (float*)d_out;

    int N = in_sizes[0] / IN_CH;   // 100000
    int E = in_sizes[2];           // 1600000

    int tb = 256;
    int nblk = (N + tb - 1) / tb;
    int eblk = (E + tb - 1) / tb;
    int nb_scan = (N + 1023) / 1024;

    // ---- CSR build + degree ----
    k_init<<<nblk, tb>>>(N);
    k_count_deg<<<eblk, tb>>>(ei, ew, E);
    k_scan1<<<nb_scan, 1024>>>(N);
    k_scan3<<<nblk, tb>>>(N, E, nb_scan);
    k_fill<<<eblk, tb>>>(ei, ew, E);

    int gemm_blocks = (N + 127) / 128;
    int gather_blocks = (N * 32 + tb - 1) / tb;

    // layer 1
    k_gemm_tc<IN_CH><<<gemm_blocks, tb>>>(x, W1, N, 0);   // A = half((x@W1)*dis)
    k_gather<<<gather_blocks, tb>>>(b1, N);               // B = relu(dis*(agg A) + b1)

    // layer 2
    k_gemm_tc<HID><<<gemm_blocks, tb>>>(x, W2, N, 1);     // A = half((B@W2)*dis)
    k_gather<<<gather_blocks, tb>>>(b2, N);               // B = relu(dis*(agg A) + b2)

    // pooling + head
    k_pool<<<(N + POOL_CHUNK - 1) / POOL_CHUNK, tb>>>(batch, N);
    k_head<<<1, 1024>>>(Wl, bl, out);
}